// round 5
// baseline (speedup 1.0000x reference)
#include <cuda_runtime.h>

#define B_DIM 8
#define CIN 512
#define COUT 3
#define WDIM 512
#define HW 65536           // 256*256
#define CONV_CLAMP 256.0f

// Precomputed per-(batch, in-channel) coefficient triple:
//   g_m4[b][c] = weight[o][c] * styles[b][c], o = 0..2 in .x/.y/.z
__device__ float4 g_m4[B_DIM * CIN];

// ---------------------------------------------------------------------------
// Kernel 1: styles + coefficient precompute.
// One warp computes one (b, c): dot(w[b,:], affine_w[c,:]) with coalesced
// loads over the WDIM axis, warp shfl-reduce, then writes 3 coefficients.
// grid = (CIN / 8, B), block = 256 (8 warps)
// ---------------------------------------------------------------------------
__global__ void styles_kernel(const float* __restrict__ w,
                              const float* __restrict__ weight,
                              const float* __restrict__ affine_w,
                              const float* __restrict__ affine_b)
{
    __shared__ float w_s[WDIM];
    const int b   = blockIdx.y;
    const int tid = threadIdx.x;

    for (int k = tid; k < WDIM; k += blockDim.x)
        w_s[k] = w[b * WDIM + k];
    __syncthreads();

    const int warp = tid >> 5;
    const int lane = tid & 31;
    const int c = blockIdx.x * (blockDim.x >> 5) + warp;
    if (c >= CIN) return;

    const float* __restrict__ arow = affine_w + (size_t)c * WDIM;
    float sum = 0.0f;
#pragma unroll
    for (int j = 0; j < WDIM / 32; ++j) {
        const int k = lane + 32 * j;
        sum = fmaf(arow[k], w_s[k], sum);
    }
#pragma unroll
    for (int off = 16; off > 0; off >>= 1)
        sum += __shfl_xor_sync(0xffffffffu, sum, off);

    if (lane == 0) {
        const float affine_gain = 1.0f / sqrtf((float)WDIM);
        const float cin_gain    = 1.0f / sqrtf((float)CIN);
        const float style = (sum * affine_gain + affine_b[c]) * cin_gain;
        float4 m;
        m.x = weight[0 * CIN + c] * style;
        m.y = weight[1 * CIN + c] * style;
        m.z = weight[2 * CIN + c] * style;
        m.w = 0.0f;
        g_m4[b * CIN + c] = m;
    }
}

// ---------------------------------------------------------------------------
// Kernel 2: the streaming reduction.
//   out[b][o][hw] = clamp( sum_c m[b][o][c] * x[b][c][hw] + bias[o] )
// R5: WIDER per-CTA streams. Evidence: 512 CTAs (4KB/c stripes) -> 88.7%
// HBM; 1024 CTAs (2KB stripes) -> 75%. Concurrently-open DRAM row regions
// scale with CTA count. So: 256 CTAs, 256 threads, each thread owns TWO
// float4 columns (hw4, hw4+256) -> 8KB contiguous per CTA per c-step,
// 2 independent LDG.128 per thread per c (double MLP).
// grid = (HW/4/512 = 32, B), block = 256
// ---------------------------------------------------------------------------
__global__ void __launch_bounds__(256)
torgb_kernel(const float* __restrict__ x,
             const float* __restrict__ bias,
             float* __restrict__ out)
{
    __shared__ float m0[CIN];
    __shared__ float m1[CIN];
    __shared__ float m2[CIN];

    const int b   = blockIdx.y;
    const int tid = threadIdx.x;

    for (int c = tid; c < CIN; c += blockDim.x) {
        const float4 m = g_m4[b * CIN + c];
        m0[c] = m.x;
        m1[c] = m.y;
        m2[c] = m.z;
    }
    __syncthreads();

    // two float4 columns per thread: p and p+256 (contiguous 8KB CTA stripe)
    const int p = blockIdx.x * 512 + tid;       // column 0 (float4 units)
    const int q = p + 256;                      // column 1
    const float4* __restrict__ x4 =
        (const float4*)(x + (size_t)b * CIN * HW);

    float4 a0 = make_float4(0.f, 0.f, 0.f, 0.f);
    float4 a1 = make_float4(0.f, 0.f, 0.f, 0.f);
    float4 a2 = make_float4(0.f, 0.f, 0.f, 0.f);
    float4 b0 = make_float4(0.f, 0.f, 0.f, 0.f);
    float4 b1 = make_float4(0.f, 0.f, 0.f, 0.f);
    float4 b2 = make_float4(0.f, 0.f, 0.f, 0.f);

#pragma unroll 4
    for (int c = 0; c < CIN; ++c) {
        const size_t rowb = (size_t)c * (HW / 4);
        const float4 xv = __ldcs(&x4[rowb + p]);
        const float4 yv = __ldcs(&x4[rowb + q]);
        const float c0 = m0[c];
        const float c1 = m1[c];
        const float c2 = m2[c];
        a0.x = fmaf(xv.x, c0, a0.x); a0.y = fmaf(xv.y, c0, a0.y);
        a0.z = fmaf(xv.z, c0, a0.z); a0.w = fmaf(xv.w, c0, a0.w);
        a1.x = fmaf(xv.x, c1, a1.x); a1.y = fmaf(xv.y, c1, a1.y);
        a1.z = fmaf(xv.z, c1, a1.z); a1.w = fmaf(xv.w, c1, a1.w);
        a2.x = fmaf(xv.x, c2, a2.x); a2.y = fmaf(xv.y, c2, a2.y);
        a2.z = fmaf(xv.z, c2, a2.z); a2.w = fmaf(xv.w, c2, a2.w);
        b0.x = fmaf(yv.x, c0, b0.x); b0.y = fmaf(yv.y, c0, b0.y);
        b0.z = fmaf(yv.z, c0, b0.z); b0.w = fmaf(yv.w, c0, b0.w);
        b1.x = fmaf(yv.x, c1, b1.x); b1.y = fmaf(yv.y, c1, b1.y);
        b1.z = fmaf(yv.z, c1, b1.z); b1.w = fmaf(yv.w, c1, b1.w);
        b2.x = fmaf(yv.x, c2, b2.x); b2.y = fmaf(yv.y, c2, b2.y);
        b2.z = fmaf(yv.z, c2, b2.z); b2.w = fmaf(yv.w, c2, b2.w);
    }

    const float bv0 = bias[0];
    const float bv1 = bias[1];
    const float bv2 = bias[2];

#define CLAMP1(v) fminf(fmaxf((v), -CONV_CLAMP), CONV_CLAMP)
#define CLAMP4(r, a, bv)                                      \
    r = make_float4(CLAMP1((a).x + (bv)), CLAMP1((a).y + (bv)), \
                    CLAMP1((a).z + (bv)), CLAMP1((a).w + (bv)))
    float4 o0, o1, o2, p0, p1, p2;
    CLAMP4(o0, a0, bv0); CLAMP4(o1, a1, bv1); CLAMP4(o2, a2, bv2);
    CLAMP4(p0, b0, bv0); CLAMP4(p1, b1, bv1); CLAMP4(p2, b2, bv2);
#undef CLAMP4
#undef CLAMP1

    float4* __restrict__ out4 = (float4*)out;
    const size_t obase = (size_t)b * COUT * (HW / 4);
    __stcs(&out4[obase + 0 * (HW / 4) + p], o0);
    __stcs(&out4[obase + 1 * (HW / 4) + p], o1);
    __stcs(&out4[obase + 2 * (HW / 4) + p], o2);
    __stcs(&out4[obase + 0 * (HW / 4) + q], p0);
    __stcs(&out4[obase + 1 * (HW / 4) + q], p1);
    __stcs(&out4[obase + 2 * (HW / 4) + q], p2);
}

// ---------------------------------------------------------------------------
// Launch
//   d_in[0] = x        [B, CIN, H, W]  f32
//   d_in[1] = w        [B, WDIM]       f32
//   d_in[2] = weight   [COUT, CIN,1,1] f32
//   d_in[3] = bias     [COUT]          f32
//   d_in[4] = affine_w [CIN, WDIM]     f32
//   d_in[5] = affine_b [CIN]           f32
// ---------------------------------------------------------------------------
extern "C" void kernel_launch(void* const* d_in, const int* in_sizes, int n_in,
                              void* d_out, int out_size)
{
    const float* x        = (const float*)d_in[0];
    const float* w        = (const float*)d_in[1];
    const float* weight   = (const float*)d_in[2];
    const float* bias     = (const float*)d_in[3];
    const float* affine_w = (const float*)d_in[4];
    const float* affine_b = (const float*)d_in[5];
    float* out = (float*)d_out;

    dim3 sgrid(CIN / 8, B_DIM);
    styles_kernel<<<sgrid, 256>>>(w, weight, affine_w, affine_b);

    dim3 cgrid(HW / 4 / 512, B_DIM);
    torgb_kernel<<<cgrid, 256>>>(x, bias, out);
}

// round 6
// speedup vs baseline: 1.5177x; 1.5177x over previous
#include <cuda_runtime.h>

#define B_DIM 8
#define CIN 512
#define COUT 3
#define WDIM 512
#define HW 65536           // 256*256
#define CONV_CLAMP 256.0f

// Precomputed per-(batch, in-channel) coefficient triple:
//   g_m4[b][c] = weight[o][c] * styles[b][c], o = 0..2 in .x/.y/.z
__device__ float4 g_m4[B_DIM * CIN];

// ---------------------------------------------------------------------------
// Kernel 1: styles + coefficient precompute.
// One warp computes one (b, c): dot(w[b,:], affine_w[c,:]) with coalesced
// loads over the WDIM axis, warp shfl-reduce, then writes 3 coefficients.
// grid = (CIN / 8, B), block = 256 (8 warps)
// ---------------------------------------------------------------------------
__global__ void styles_kernel(const float* __restrict__ w,
                              const float* __restrict__ weight,
                              const float* __restrict__ affine_w,
                              const float* __restrict__ affine_b)
{
    __shared__ float w_s[WDIM];
    const int b   = blockIdx.y;
    const int tid = threadIdx.x;

    for (int k = tid; k < WDIM; k += blockDim.x)
        w_s[k] = w[b * WDIM + k];
    __syncthreads();

    const int warp = tid >> 5;
    const int lane = tid & 31;
    const int c = blockIdx.x * (blockDim.x >> 5) + warp;
    if (c >= CIN) return;

    const float* __restrict__ arow = affine_w + (size_t)c * WDIM;
    float sum = 0.0f;
#pragma unroll
    for (int j = 0; j < WDIM / 32; ++j) {
        const int k = lane + 32 * j;
        sum = fmaf(arow[k], w_s[k], sum);
    }
#pragma unroll
    for (int off = 16; off > 0; off >>= 1)
        sum += __shfl_xor_sync(0xffffffffu, sum, off);

    if (lane == 0) {
        const float affine_gain = 1.0f / sqrtf((float)WDIM);
        const float cin_gain    = 1.0f / sqrtf((float)CIN);
        const float style = (sum * affine_gain + affine_b[c]) * cin_gain;
        float4 m;
        m.x = weight[0 * CIN + c] * style;
        m.y = weight[1 * CIN + c] * style;
        m.z = weight[2 * CIN + c] * style;
        m.w = 0.0f;
        g_m4[b * CIN + c] = m;
    }
}

// ---------------------------------------------------------------------------
// Kernel 2: the streaming reduction.
//   out[b][o][hw] = clamp( sum_c m[b][o][c] * x[b][c][hw] + bias[o] )
// Empirical geometry optimum (R1-R5 sweep): grid = (64, 8) = 512 CTAs,
// block = 256, one float4 column per thread, __ldcs single-use streams.
// R6 micro-opts: coefficients as float4 in smem (1x LDS.128 per c instead
// of 3x LDS.32) and unroll 8 for deeper front-batched LDG MLP.
// ---------------------------------------------------------------------------
__global__ void __launch_bounds__(256)
torgb_kernel(const float* __restrict__ x,
             const float* __restrict__ bias,
             float* __restrict__ out)
{
    __shared__ float4 sm4[CIN];   // (m0, m1, m2, 0) per channel

    const int b   = blockIdx.y;
    const int tid = threadIdx.x;

    for (int c = tid; c < CIN; c += blockDim.x)
        sm4[c] = g_m4[b * CIN + c];
    __syncthreads();

    const int hw4 = blockIdx.x * blockDim.x + tid;   // index in float4 units
    const float4* __restrict__ x4 =
        (const float4*)(x + (size_t)b * CIN * HW);

    float4 a0 = make_float4(0.f, 0.f, 0.f, 0.f);
    float4 a1 = make_float4(0.f, 0.f, 0.f, 0.f);
    float4 a2 = make_float4(0.f, 0.f, 0.f, 0.f);

#pragma unroll 8
    for (int c = 0; c < CIN; ++c) {
        const float4 xv = __ldcs(&x4[(size_t)c * (HW / 4) + hw4]);
        const float4 mc = sm4[c];
        a0.x = fmaf(xv.x, mc.x, a0.x); a0.y = fmaf(xv.y, mc.x, a0.y);
        a0.z = fmaf(xv.z, mc.x, a0.z); a0.w = fmaf(xv.w, mc.x, a0.w);
        a1.x = fmaf(xv.x, mc.y, a1.x); a1.y = fmaf(xv.y, mc.y, a1.y);
        a1.z = fmaf(xv.z, mc.y, a1.z); a1.w = fmaf(xv.w, mc.y, a1.w);
        a2.x = fmaf(xv.x, mc.z, a2.x); a2.y = fmaf(xv.y, mc.z, a2.y);
        a2.z = fmaf(xv.z, mc.z, a2.z); a2.w = fmaf(xv.w, mc.z, a2.w);
    }

    const float bv0 = bias[0];
    const float bv1 = bias[1];
    const float bv2 = bias[2];

#define CLAMP1(v) fminf(fmaxf((v), -CONV_CLAMP), CONV_CLAMP)
    float4 o0 = make_float4(CLAMP1(a0.x + bv0), CLAMP1(a0.y + bv0),
                            CLAMP1(a0.z + bv0), CLAMP1(a0.w + bv0));
    float4 o1 = make_float4(CLAMP1(a1.x + bv1), CLAMP1(a1.y + bv1),
                            CLAMP1(a1.z + bv1), CLAMP1(a1.w + bv1));
    float4 o2 = make_float4(CLAMP1(a2.x + bv2), CLAMP1(a2.y + bv2),
                            CLAMP1(a2.z + bv2), CLAMP1(a2.w + bv2));
#undef CLAMP1

    float4* __restrict__ out4 = (float4*)out;
    const size_t obase = (size_t)b * COUT * (HW / 4);
    __stcs(&out4[obase + 0 * (HW / 4) + hw4], o0);
    __stcs(&out4[obase + 1 * (HW / 4) + hw4], o1);
    __stcs(&out4[obase + 2 * (HW / 4) + hw4], o2);
}

// ---------------------------------------------------------------------------
// Launch
//   d_in[0] = x        [B, CIN, H, W]  f32
//   d_in[1] = w        [B, WDIM]       f32
//   d_in[2] = weight   [COUT, CIN,1,1] f32
//   d_in[3] = bias     [COUT]          f32
//   d_in[4] = affine_w [CIN, WDIM]     f32
//   d_in[5] = affine_b [CIN]           f32
// ---------------------------------------------------------------------------
extern "C" void kernel_launch(void* const* d_in, const int* in_sizes, int n_in,
                              void* d_out, int out_size)
{
    const float* x        = (const float*)d_in[0];
    const float* w        = (const float*)d_in[1];
    const float* weight   = (const float*)d_in[2];
    const float* bias     = (const float*)d_in[3];
    const float* affine_w = (const float*)d_in[4];
    const float* affine_b = (const float*)d_in[5];
    float* out = (float*)d_out;

    dim3 sgrid(CIN / 8, B_DIM);
    styles_kernel<<<sgrid, 256>>>(w, weight, affine_w, affine_b);

    dim3 cgrid(HW / 4 / 256, B_DIM);
    torgb_kernel<<<cgrid, 256>>>(x, bias, out);
}

// round 7
// speedup vs baseline: 1.7180x; 1.1320x over previous
#include <cuda_runtime.h>

#define B_DIM 8
#define CIN 512
#define COUT 3
#define WDIM 512
#define HW 65536           // 256*256
#define CONV_CLAMP 256.0f

// Staging for per-(batch, channel) coefficient triples:
//   g_m4[b*CIN+c] = (weight[0][c], weight[1][c], weight[2][c], 0) * styles[b][c]
__device__ float4 g_m4[B_DIM * CIN];

// Per-batch arrival counters (monotonic across graph replays; cohort = 64 CTAs.
// target = (start/64+1)*64, so no reset is needed -> deterministic per run).
__device__ unsigned int g_bar[B_DIM];

// ---------------------------------------------------------------------------
// Fused kernel.
// grid = (64, 8), block = 256. All 512 CTAs are co-resident in one wave
// (4 CTAs/SM x 148 SMs = 592 slots), so the per-batch spin barrier cannot
// deadlock.
//
// Phase 1: warp w of CTA (bx, b) computes style for channel c = bx*8+w of
//          batch b (one 512-length dot + shfl reduce) and stages g_m4[b][c].
//          Per-batch barrier: 64 CTAs arrive; spin until cohort complete.
// Phase 2: R3's byte-identical streaming loop (geometry + body frozen:
//          512x256, unroll 4, separate m0/m1/m2 smem, __ldcs/__stcs).
// ---------------------------------------------------------------------------
__global__ void __launch_bounds__(256)
torgb_fused_kernel(const float* __restrict__ x,
                   const float* __restrict__ w,
                   const float* __restrict__ weight,
                   const float* __restrict__ bias,
                   const float* __restrict__ affine_w,
                   const float* __restrict__ affine_b,
                   float* __restrict__ out)
{
    __shared__ float m0[CIN];
    __shared__ float m1[CIN];
    __shared__ float m2[CIN];

    const int b    = blockIdx.y;
    const int bx   = blockIdx.x;
    const int tid  = threadIdx.x;
    const int warp = tid >> 5;
    const int lane = tid & 31;

    // ---- Phase 1: compute this CTA's 8 coefficients (c = bx*8 + warp) ----
    {
        const int c = bx * 8 + warp;
        const float* __restrict__ arow = affine_w + (size_t)c * WDIM;
        const float* __restrict__ wrow = w + (size_t)b * WDIM;
        float sum = 0.0f;
#pragma unroll
        for (int j = 0; j < WDIM / 32; ++j) {
            const int k = lane + 32 * j;
            sum = fmaf(__ldg(&arow[k]), __ldg(&wrow[k]), sum);
        }
#pragma unroll
        for (int off = 16; off > 0; off >>= 1)
            sum += __shfl_xor_sync(0xffffffffu, sum, off);

        if (lane == 0) {
            const float affine_gain = 1.0f / sqrtf((float)WDIM);
            const float cin_gain    = 1.0f / sqrtf((float)CIN);
            const float style = (sum * affine_gain + affine_b[c]) * cin_gain;
            float4 m;
            m.x = weight[0 * CIN + c] * style;
            m.y = weight[1 * CIN + c] * style;
            m.z = weight[2 * CIN + c] * style;
            m.w = 0.0f;
            g_m4[b * CIN + c] = m;
        }
    }

    // ---- Per-batch barrier over the 64 CTAs that produce batch b ----
    __syncthreads();                 // all warps in CTA done writing
    if (tid == 0) {
        __threadfence();             // make our g_m4 writes visible
        const unsigned int start  = atomicAdd(&g_bar[b], 1u);
        const unsigned int target = (start / 64u + 1u) * 64u;
        volatile unsigned int* ctr = &g_bar[b];
        while (*ctr < target)
            __nanosleep(32);
        __threadfence();             // acquire side
    }
    __syncthreads();

    // ---- Load coefficients for batch b into smem (L2 via __ldcg) ----
    for (int c = tid; c < CIN; c += blockDim.x) {
        const float4 m = __ldcg(&g_m4[b * CIN + c]);
        m0[c] = m.x;
        m1[c] = m.y;
        m2[c] = m.z;
    }
    __syncthreads();

    // ---- Phase 2: the R3 streaming loop (frozen) ----
    const int hw4 = bx * blockDim.x + tid;           // index in float4 units
    const float4* __restrict__ x4 =
        (const float4*)(x + (size_t)b * CIN * HW);

    float4 a0 = make_float4(0.f, 0.f, 0.f, 0.f);
    float4 a1 = make_float4(0.f, 0.f, 0.f, 0.f);
    float4 a2 = make_float4(0.f, 0.f, 0.f, 0.f);

#pragma unroll 4
    for (int c = 0; c < CIN; ++c) {
        const float4 xv = __ldcs(&x4[(size_t)c * (HW / 4) + hw4]);
        const float c0 = m0[c];
        const float c1 = m1[c];
        const float c2 = m2[c];
        a0.x = fmaf(xv.x, c0, a0.x); a0.y = fmaf(xv.y, c0, a0.y);
        a0.z = fmaf(xv.z, c0, a0.z); a0.w = fmaf(xv.w, c0, a0.w);
        a1.x = fmaf(xv.x, c1, a1.x); a1.y = fmaf(xv.y, c1, a1.y);
        a1.z = fmaf(xv.z, c1, a1.z); a1.w = fmaf(xv.w, c1, a1.w);
        a2.x = fmaf(xv.x, c2, a2.x); a2.y = fmaf(xv.y, c2, a2.y);
        a2.z = fmaf(xv.z, c2, a2.z); a2.w = fmaf(xv.w, c2, a2.w);
    }

    const float bv0 = bias[0];
    const float bv1 = bias[1];
    const float bv2 = bias[2];

#define CLAMP1(v) fminf(fmaxf((v), -CONV_CLAMP), CONV_CLAMP)
    float4 o0 = make_float4(CLAMP1(a0.x + bv0), CLAMP1(a0.y + bv0),
                            CLAMP1(a0.z + bv0), CLAMP1(a0.w + bv0));
    float4 o1 = make_float4(CLAMP1(a1.x + bv1), CLAMP1(a1.y + bv1),
                            CLAMP1(a1.z + bv1), CLAMP1(a1.w + bv1));
    float4 o2 = make_float4(CLAMP1(a2.x + bv2), CLAMP1(a2.y + bv2),
                            CLAMP1(a2.z + bv2), CLAMP1(a2.w + bv2));
#undef CLAMP1

    float4* __restrict__ out4 = (float4*)out;
    const size_t obase = (size_t)b * COUT * (HW / 4);
    __stcs(&out4[obase + 0 * (HW / 4) + hw4], o0);
    __stcs(&out4[obase + 1 * (HW / 4) + hw4], o1);
    __stcs(&out4[obase + 2 * (HW / 4) + hw4], o2);
}

// ---------------------------------------------------------------------------
// Launch
//   d_in[0] = x        [B, CIN, H, W]  f32
//   d_in[1] = w        [B, WDIM]       f32
//   d_in[2] = weight   [COUT, CIN,1,1] f32
//   d_in[3] = bias     [COUT]          f32
//   d_in[4] = affine_w [CIN, WDIM]     f32
//   d_in[5] = affine_b [CIN]           f32
// ---------------------------------------------------------------------------
extern "C" void kernel_launch(void* const* d_in, const int* in_sizes, int n_in,
                              void* d_out, int out_size)
{
    const float* x        = (const float*)d_in[0];
    const float* w        = (const float*)d_in[1];
    const float* weight   = (const float*)d_in[2];
    const float* bias     = (const float*)d_in[3];
    const float* affine_w = (const float*)d_in[4];
    const float* affine_b = (const float*)d_in[5];
    float* out = (float*)d_out;

    dim3 cgrid(HW / 4 / 256, B_DIM);
    torgb_fused_kernel<<<cgrid, 256>>>(x, w, weight, bias,
                                       affine_w, affine_b, out);
}